// round 12
// baseline (speedup 1.0000x reference)
#include <cuda_runtime.h>
#include <math.h>

// Problem constants
#define D_MODEL   1024
#define NUM_HEADS 16
#define DK        64
#define SEQ       2048
#define BATCH     2
#define M_TOK     (BATCH * SEQ)   // 4096 tokens

// Scratch (device globals — no cudaMalloc allowed)
__device__ float g_Q [M_TOK * D_MODEL];
__device__ float g_K [M_TOK * D_MODEL];
__device__ float g_V [M_TOK * D_MODEL];
__device__ float g_AO[M_TOK * D_MODEL];

// ---------------------------------------------------------------------------
// GEMM (NT): C[m][n] = sum_k A[m][k] * W[n][k]  (+ bias[n] if bias != nullptr)
// M=4096, N=1024, K=1024. BM=BN=128, BK=16, 256 threads, 8x8 per thread.
// ---------------------------------------------------------------------------
__global__ __launch_bounds__(256, 2)
void gemm_nt_kernel(const float* __restrict__ A, const float* __restrict__ W,
                    const float* __restrict__ bias, float* __restrict__ C) {
    const int K = D_MODEL, N = D_MODEL;
    __shared__ float as[16][132];   // [k][m], pad 132 (16B-aligned rows)
    __shared__ float bs[16][132];   // [k][n]

    const int t  = threadIdx.x;
    const int tx = t & 15;
    const int ty = t >> 4;
    const int m0 = blockIdx.y * 128;
    const int n0 = blockIdx.x * 128;

    float acc[8][8];
#pragma unroll
    for (int i = 0; i < 8; i++)
#pragma unroll
        for (int j = 0; j < 8; j++) acc[i][j] = 0.f;

    const float* Ab = A + (size_t)m0 * K;
    const float* Wb = W + (size_t)n0 * K;

    for (int k0 = 0; k0 < K; k0 += 16) {
        // load tiles (transposed into [k][m] layout)
#pragma unroll
        for (int l = 0; l < 2; l++) {
            int fid = t + l * 256;          // 0..511
            int m   = fid >> 2;             // 0..127
            int kq  = (fid & 3) << 2;       // 0,4,8,12
            float4 av = *(const float4*)(Ab + (size_t)m * K + k0 + kq);
            as[kq + 0][m] = av.x; as[kq + 1][m] = av.y;
            as[kq + 2][m] = av.z; as[kq + 3][m] = av.w;
            float4 bv = *(const float4*)(Wb + (size_t)m * K + k0 + kq);
            bs[kq + 0][m] = bv.x; bs[kq + 1][m] = bv.y;
            bs[kq + 2][m] = bv.z; bs[kq + 3][m] = bv.w;
        }
        __syncthreads();

#pragma unroll
        for (int k = 0; k < 16; k++) {
            float af[8], bf[8];
            *(float4*)&af[0] = *(const float4*)&as[k][ty * 8];
            *(float4*)&af[4] = *(const float4*)&as[k][ty * 8 + 4];
            *(float4*)&bf[0] = *(const float4*)&bs[k][tx * 8];
            *(float4*)&bf[4] = *(const float4*)&bs[k][tx * 8 + 4];
#pragma unroll
            for (int i = 0; i < 8; i++)
#pragma unroll
                for (int j = 0; j < 8; j++)
                    acc[i][j] += af[i] * bf[j];
        }
        __syncthreads();
    }

    float bv[8];
#pragma unroll
    for (int j = 0; j < 8; j++) bv[j] = bias ? bias[n0 + tx * 8 + j] : 0.f;

#pragma unroll
    for (int i = 0; i < 8; i++) {
        float* cp = C + (size_t)(m0 + ty * 8 + i) * N + n0 + tx * 8;
        float4 o0 = make_float4(acc[i][0] + bv[0], acc[i][1] + bv[1],
                                acc[i][2] + bv[2], acc[i][3] + bv[3]);
        float4 o1 = make_float4(acc[i][4] + bv[4], acc[i][5] + bv[5],
                                acc[i][6] + bv[6], acc[i][7] + bv[7]);
        *(float4*)cp       = o0;
        *(float4*)(cp + 4) = o1;
    }
}

// ---------------------------------------------------------------------------
// Flash attention (fp32, online softmax).
// Grid: (S/64, H, B). 256 threads as 16x16. Each CTA: 64 query rows, one head.
// Loops over 32 KV blocks of 64 keys. SMEM: qt/kt [d][i|j], vs [j][d],
// ps [i][j], all padded to 65 floats/row (conflict-free).
// ---------------------------------------------------------------------------
#define ATTN_SMEM_FLOATS (4 * 64 * 65)
#define ATTN_SMEM_BYTES  (ATTN_SMEM_FLOATS * sizeof(float))

__global__ __launch_bounds__(256)
void attn_kernel(const float* __restrict__ Qg, const float* __restrict__ Kg,
                 const float* __restrict__ Vg, float* __restrict__ Og) {
    extern __shared__ float sm[];
    float* qt = sm;                 // qt[d*65 + i], Q^T (pre-scaled)
    float* kt = sm + 64 * 65;       // kt[d*65 + j], K^T
    float* vs = sm + 2 * 64 * 65;   // vs[j*65 + d], V
    float* ps = sm + 3 * 64 * 65;   // ps[i*65 + j], P

    const int t  = threadIdx.x;
    const int tx = t & 15;
    const int ty = t >> 4;
    const int h  = blockIdx.y;
    const int b  = blockIdx.z;
    const int m0 = b * SEQ + blockIdx.x * 64;   // global query row base
    const int cb = h * DK;                      // column base in [M,1024]

    // Load Q tile (scaled by 1/sqrt(Dk) = 0.125)
#pragma unroll
    for (int r = 0; r < 16; r++) {
        int idx = t + r * 256;
        int i = idx >> 6, d = idx & 63;
        qt[d * 65 + i] = Qg[(size_t)(m0 + i) * D_MODEL + cb + d] * 0.125f;
    }

    float m_i[4], l_i[4], o[4][4];
#pragma unroll
    for (int ii = 0; ii < 4; ii++) {
        m_i[ii] = -1e30f;
        l_i[ii] = 0.f;
#pragma unroll
        for (int kk = 0; kk < 4; kk++) o[ii][kk] = 0.f;
    }

    for (int kv = 0; kv < SEQ / 64; kv++) {
        const int k0 = b * SEQ + kv * 64;
        __syncthreads();   // previous O-GEMM done before overwriting kt/vs
#pragma unroll
        for (int r = 0; r < 16; r++) {
            int idx = t + r * 256;
            int j = idx >> 6, d = idx & 63;
            kt[d * 65 + j] = Kg[(size_t)(k0 + j) * D_MODEL + cb + d];
            vs[j * 65 + d] = Vg[(size_t)(k0 + j) * D_MODEL + cb + d];
        }
        __syncthreads();

        // S = Q K^T (scale already folded into Q)
        float s[4][4];
#pragma unroll
        for (int ii = 0; ii < 4; ii++)
#pragma unroll
            for (int jj = 0; jj < 4; jj++) s[ii][jj] = 0.f;

#pragma unroll 4
        for (int d = 0; d < 64; d++) {
            float qf[4], kf[4];
#pragma unroll
            for (int ii = 0; ii < 4; ii++) qf[ii] = qt[d * 65 + ty * 4 + ii];
#pragma unroll
            for (int jj = 0; jj < 4; jj++) kf[jj] = kt[d * 65 + tx * 4 + jj];
#pragma unroll
            for (int ii = 0; ii < 4; ii++)
#pragma unroll
                for (int jj = 0; jj < 4; jj++)
                    s[ii][jj] += qf[ii] * kf[jj];
        }

        // online softmax update (row reductions across the 16 tx lanes)
#pragma unroll
        for (int ii = 0; ii < 4; ii++) {
            float mb = fmaxf(fmaxf(s[ii][0], s[ii][1]), fmaxf(s[ii][2], s[ii][3]));
#pragma unroll
            for (int off = 1; off < 16; off <<= 1)
                mb = fmaxf(mb, __shfl_xor_sync(0xffffffffu, mb, off));
            float mn    = fmaxf(m_i[ii], mb);
            float alpha = __expf(m_i[ii] - mn);
            float rs = 0.f;
#pragma unroll
            for (int jj = 0; jj < 4; jj++) {
                s[ii][jj] = __expf(s[ii][jj] - mn);
                rs += s[ii][jj];
            }
#pragma unroll
            for (int off = 1; off < 16; off <<= 1)
                rs += __shfl_xor_sync(0xffffffffu, rs, off);
            l_i[ii] = l_i[ii] * alpha + rs;
            m_i[ii] = mn;
#pragma unroll
            for (int kk = 0; kk < 4; kk++) o[ii][kk] *= alpha;
#pragma unroll
            for (int jj = 0; jj < 4; jj++)
                ps[(ty * 4 + ii) * 65 + tx * 4 + jj] = s[ii][jj];
        }
        __syncthreads();

        // O += P @ V
#pragma unroll 4
        for (int j = 0; j < 64; j++) {
            float pf[4], vf[4];
#pragma unroll
            for (int ii = 0; ii < 4; ii++) pf[ii] = ps[(ty * 4 + ii) * 65 + j];
#pragma unroll
            for (int kk = 0; kk < 4; kk++) vf[kk] = vs[j * 65 + tx * 4 + kk];
#pragma unroll
            for (int ii = 0; ii < 4; ii++)
#pragma unroll
                for (int kk = 0; kk < 4; kk++)
                    o[ii][kk] += pf[ii] * vf[kk];
        }
    }

    // finalize: divide by l, write to [M, 1024] layout (head h columns)
#pragma unroll
    for (int ii = 0; ii < 4; ii++) {
        float inv = 1.f / l_i[ii];
        float4 ov = make_float4(o[ii][0] * inv, o[ii][1] * inv,
                                o[ii][2] * inv, o[ii][3] * inv);
        *(float4*)(Og + (size_t)(m0 + ty * 4 + ii) * D_MODEL + cb + tx * 4) = ov;
    }
}

// ---------------------------------------------------------------------------
// Launch: 3 projection GEMMs -> flash attention -> output projection (+bias)
// ---------------------------------------------------------------------------
extern "C" void kernel_launch(void* const* d_in, const int* in_sizes, int n_in,
                              void* d_out, int out_size) {
    const float* x  = (const float*)d_in[0];
    const float* wq = (const float*)d_in[1];
    const float* wk = (const float*)d_in[2];
    const float* wv = (const float*)d_in[3];
    const float* wo = (const float*)d_in[4];
    const float* bo = (const float*)d_in[5];
    float* out = (float*)d_out;

    float *Qp, *Kp, *Vp, *AOp;
    cudaGetSymbolAddress((void**)&Qp,  g_Q);
    cudaGetSymbolAddress((void**)&Kp,  g_K);
    cudaGetSymbolAddress((void**)&Vp,  g_V);
    cudaGetSymbolAddress((void**)&AOp, g_AO);

    cudaFuncSetAttribute(attn_kernel,
                         cudaFuncAttributeMaxDynamicSharedMemorySize,
                         (int)ATTN_SMEM_BYTES);

    dim3 gemm_grid(D_MODEL / 128, M_TOK / 128);   // (8, 32)
    gemm_nt_kernel<<<gemm_grid, 256>>>(x, wq, nullptr, Qp);
    gemm_nt_kernel<<<gemm_grid, 256>>>(x, wk, nullptr, Kp);
    gemm_nt_kernel<<<gemm_grid, 256>>>(x, wv, nullptr, Vp);

    dim3 attn_grid(SEQ / 64, NUM_HEADS, BATCH);   // (32, 16, 2)
    attn_kernel<<<attn_grid, 256, ATTN_SMEM_BYTES>>>(Qp, Kp, Vp, AOp);

    gemm_nt_kernel<<<gemm_grid, 256>>>(AOp, wo, bo, out);
}

// round 13
// speedup vs baseline: 1.0007x; 1.0007x over previous
#include <cuda_runtime.h>
#include <math.h>

// Problem constants
#define D_MODEL   1024
#define NUM_HEADS 16
#define DK        64
#define SEQ       2048
#define BATCH     2
#define M_TOK     (BATCH * SEQ)   // 4096 tokens

// Scratch (device globals — no cudaMalloc allowed)
__device__ float g_Q [M_TOK * D_MODEL];
__device__ float g_K [M_TOK * D_MODEL];
__device__ float g_V [M_TOK * D_MODEL];
__device__ float g_AO[M_TOK * D_MODEL];

// ---------------------------------------------------------------------------
// GEMM (NT): C[m][n] = sum_k A[m][k] * W[n][k]  (+ bias[n] if bias != nullptr)
// M=4096, N=1024, K=1024. BM=BN=128, BK=16, 256 threads, 8x8 per thread.
// ---------------------------------------------------------------------------
__global__ __launch_bounds__(256, 2)
void gemm_nt_kernel(const float* __restrict__ A, const float* __restrict__ W,
                    const float* __restrict__ bias, float* __restrict__ C) {
    const int K = D_MODEL, N = D_MODEL;
    __shared__ float as[16][132];   // [k][m], pad 132 (16B-aligned rows)
    __shared__ float bs[16][132];   // [k][n]

    const int t  = threadIdx.x;
    const int tx = t & 15;
    const int ty = t >> 4;
    const int m0 = blockIdx.y * 128;
    const int n0 = blockIdx.x * 128;

    float acc[8][8];
#pragma unroll
    for (int i = 0; i < 8; i++)
#pragma unroll
        for (int j = 0; j < 8; j++) acc[i][j] = 0.f;

    const float* Ab = A + (size_t)m0 * K;
    const float* Wb = W + (size_t)n0 * K;

    for (int k0 = 0; k0 < K; k0 += 16) {
        // load tiles (transposed into [k][m] layout)
#pragma unroll
        for (int l = 0; l < 2; l++) {
            int fid = t + l * 256;          // 0..511
            int m   = fid >> 2;             // 0..127
            int kq  = (fid & 3) << 2;       // 0,4,8,12
            float4 av = *(const float4*)(Ab + (size_t)m * K + k0 + kq);
            as[kq + 0][m] = av.x; as[kq + 1][m] = av.y;
            as[kq + 2][m] = av.z; as[kq + 3][m] = av.w;
            float4 bv = *(const float4*)(Wb + (size_t)m * K + k0 + kq);
            bs[kq + 0][m] = bv.x; bs[kq + 1][m] = bv.y;
            bs[kq + 2][m] = bv.z; bs[kq + 3][m] = bv.w;
        }
        __syncthreads();

#pragma unroll
        for (int k = 0; k < 16; k++) {
            float af[8], bf[8];
            *(float4*)&af[0] = *(const float4*)&as[k][ty * 8];
            *(float4*)&af[4] = *(const float4*)&as[k][ty * 8 + 4];
            *(float4*)&bf[0] = *(const float4*)&bs[k][tx * 8];
            *(float4*)&bf[4] = *(const float4*)&bs[k][tx * 8 + 4];
#pragma unroll
            for (int i = 0; i < 8; i++)
#pragma unroll
                for (int j = 0; j < 8; j++)
                    acc[i][j] += af[i] * bf[j];
        }
        __syncthreads();
    }

    float bv[8];
#pragma unroll
    for (int j = 0; j < 8; j++) bv[j] = bias ? bias[n0 + tx * 8 + j] : 0.f;

#pragma unroll
    for (int i = 0; i < 8; i++) {
        float* cp = C + (size_t)(m0 + ty * 8 + i) * N + n0 + tx * 8;
        float4 o0 = make_float4(acc[i][0] + bv[0], acc[i][1] + bv[1],
                                acc[i][2] + bv[2], acc[i][3] + bv[3]);
        float4 o1 = make_float4(acc[i][4] + bv[4], acc[i][5] + bv[5],
                                acc[i][6] + bv[6], acc[i][7] + bv[7]);
        *(float4*)cp       = o0;
        *(float4*)(cp + 4) = o1;
    }
}

// ---------------------------------------------------------------------------
// Flash attention (fp32, online softmax).
// Grid: (S/64, H, B). 256 threads as 16x16. Each CTA: 64 query rows, one head.
// Loops over 32 KV blocks of 64 keys. SMEM: qt/kt [d][i|j], vs [j][d],
// ps [i][j], all padded to 65 floats/row (conflict-free).
// ---------------------------------------------------------------------------
#define ATTN_SMEM_FLOATS (4 * 64 * 65)
#define ATTN_SMEM_BYTES  (ATTN_SMEM_FLOATS * sizeof(float))

__global__ __launch_bounds__(256)
void attn_kernel(const float* __restrict__ Qg, const float* __restrict__ Kg,
                 const float* __restrict__ Vg, float* __restrict__ Og) {
    extern __shared__ float sm[];
    float* qt = sm;                 // qt[d*65 + i], Q^T (pre-scaled)
    float* kt = sm + 64 * 65;       // kt[d*65 + j], K^T
    float* vs = sm + 2 * 64 * 65;   // vs[j*65 + d], V
    float* ps = sm + 3 * 64 * 65;   // ps[i*65 + j], P

    const int t  = threadIdx.x;
    const int tx = t & 15;
    const int ty = t >> 4;
    const int h  = blockIdx.y;
    const int b  = blockIdx.z;
    const int m0 = b * SEQ + blockIdx.x * 64;   // global query row base
    const int cb = h * DK;                      // column base in [M,1024]

    // Load Q tile (scaled by 1/sqrt(Dk) = 0.125)
#pragma unroll
    for (int r = 0; r < 16; r++) {
        int idx = t + r * 256;
        int i = idx >> 6, d = idx & 63;
        qt[d * 65 + i] = Qg[(size_t)(m0 + i) * D_MODEL + cb + d] * 0.125f;
    }

    float m_i[4], l_i[4], o[4][4];
#pragma unroll
    for (int ii = 0; ii < 4; ii++) {
        m_i[ii] = -1e30f;
        l_i[ii] = 0.f;
#pragma unroll
        for (int kk = 0; kk < 4; kk++) o[ii][kk] = 0.f;
    }

    for (int kv = 0; kv < SEQ / 64; kv++) {
        const int k0 = b * SEQ + kv * 64;
        __syncthreads();   // previous O-GEMM done before overwriting kt/vs
#pragma unroll
        for (int r = 0; r < 16; r++) {
            int idx = t + r * 256;
            int j = idx >> 6, d = idx & 63;
            kt[d * 65 + j] = Kg[(size_t)(k0 + j) * D_MODEL + cb + d];
            vs[j * 65 + d] = Vg[(size_t)(k0 + j) * D_MODEL + cb + d];
        }
        __syncthreads();

        // S = Q K^T (scale already folded into Q)
        float s[4][4];
#pragma unroll
        for (int ii = 0; ii < 4; ii++)
#pragma unroll
            for (int jj = 0; jj < 4; jj++) s[ii][jj] = 0.f;

#pragma unroll 4
        for (int d = 0; d < 64; d++) {
            float qf[4], kf[4];
#pragma unroll
            for (int ii = 0; ii < 4; ii++) qf[ii] = qt[d * 65 + ty * 4 + ii];
#pragma unroll
            for (int jj = 0; jj < 4; jj++) kf[jj] = kt[d * 65 + tx * 4 + jj];
#pragma unroll
            for (int ii = 0; ii < 4; ii++)
#pragma unroll
                for (int jj = 0; jj < 4; jj++)
                    s[ii][jj] += qf[ii] * kf[jj];
        }

        // online softmax update (row reductions across the 16 tx lanes)
#pragma unroll
        for (int ii = 0; ii < 4; ii++) {
            float mb = fmaxf(fmaxf(s[ii][0], s[ii][1]), fmaxf(s[ii][2], s[ii][3]));
#pragma unroll
            for (int off = 1; off < 16; off <<= 1)
                mb = fmaxf(mb, __shfl_xor_sync(0xffffffffu, mb, off));
            float mn    = fmaxf(m_i[ii], mb);
            float alpha = __expf(m_i[ii] - mn);
            float rs = 0.f;
#pragma unroll
            for (int jj = 0; jj < 4; jj++) {
                s[ii][jj] = __expf(s[ii][jj] - mn);
                rs += s[ii][jj];
            }
#pragma unroll
            for (int off = 1; off < 16; off <<= 1)
                rs += __shfl_xor_sync(0xffffffffu, rs, off);
            l_i[ii] = l_i[ii] * alpha + rs;
            m_i[ii] = mn;
#pragma unroll
            for (int kk = 0; kk < 4; kk++) o[ii][kk] *= alpha;
#pragma unroll
            for (int jj = 0; jj < 4; jj++)
                ps[(ty * 4 + ii) * 65 + tx * 4 + jj] = s[ii][jj];
        }
        __syncthreads();

        // O += P @ V
#pragma unroll 4
        for (int j = 0; j < 64; j++) {
            float pf[4], vf[4];
#pragma unroll
            for (int ii = 0; ii < 4; ii++) pf[ii] = ps[(ty * 4 + ii) * 65 + j];
#pragma unroll
            for (int kk = 0; kk < 4; kk++) vf[kk] = vs[j * 65 + tx * 4 + kk];
#pragma unroll
            for (int ii = 0; ii < 4; ii++)
#pragma unroll
                for (int kk = 0; kk < 4; kk++)
                    o[ii][kk] += pf[ii] * vf[kk];
        }
    }

    // finalize: divide by l, write to [M, 1024] layout (head h columns)
#pragma unroll
    for (int ii = 0; ii < 4; ii++) {
        float inv = 1.f / l_i[ii];
        float4 ov = make_float4(o[ii][0] * inv, o[ii][1] * inv,
                                o[ii][2] * inv, o[ii][3] * inv);
        *(float4*)(Og + (size_t)(m0 + ty * 4 + ii) * D_MODEL + cb + tx * 4) = ov;
    }
}

// ---------------------------------------------------------------------------
// Launch: 3 projection GEMMs -> flash attention -> output projection (+bias)
// ---------------------------------------------------------------------------
extern "C" void kernel_launch(void* const* d_in, const int* in_sizes, int n_in,
                              void* d_out, int out_size) {
    const float* x  = (const float*)d_in[0];
    const float* wq = (const float*)d_in[1];
    const float* wk = (const float*)d_in[2];
    const float* wv = (const float*)d_in[3];
    const float* wo = (const float*)d_in[4];
    const float* bo = (const float*)d_in[5];
    float* out = (float*)d_out;

    float *Qp, *Kp, *Vp, *AOp;
    cudaGetSymbolAddress((void**)&Qp,  g_Q);
    cudaGetSymbolAddress((void**)&Kp,  g_K);
    cudaGetSymbolAddress((void**)&Vp,  g_V);
    cudaGetSymbolAddress((void**)&AOp, g_AO);

    cudaFuncSetAttribute(attn_kernel,
                         cudaFuncAttributeMaxDynamicSharedMemorySize,
                         (int)ATTN_SMEM_BYTES);

    dim3 gemm_grid(D_MODEL / 128, M_TOK / 128);   // (8, 32)
    gemm_nt_kernel<<<gemm_grid, 256>>>(x, wq, nullptr, Qp);
    gemm_nt_kernel<<<gemm_grid, 256>>>(x, wk, nullptr, Kp);
    gemm_nt_kernel<<<gemm_grid, 256>>>(x, wv, nullptr, Vp);

    dim3 attn_grid(SEQ / 64, NUM_HEADS, BATCH);   // (32, 16, 2)
    attn_kernel<<<attn_grid, 256, ATTN_SMEM_BYTES>>>(Qp, Kp, Vp, AOp);

    gemm_nt_kernel<<<gemm_grid, 256>>>(AOp, wo, bo, out);
}

// round 14
// speedup vs baseline: 1.0014x; 1.0007x over previous
#include <cuda_runtime.h>
#include <math.h>

// Problem constants
#define D_MODEL   1024
#define NUM_HEADS 16
#define DK        64
#define SEQ       2048
#define BATCH     2
#define M_TOK     (BATCH * SEQ)   // 4096 tokens

// Scratch (device globals — no cudaMalloc allowed)
__device__ float g_Q [M_TOK * D_MODEL];
__device__ float g_K [M_TOK * D_MODEL];
__device__ float g_V [M_TOK * D_MODEL];
__device__ float g_AO[M_TOK * D_MODEL];

// ---------------------------------------------------------------------------
// GEMM (NT): C[m][n] = sum_k A[m][k] * W[n][k]  (+ bias[n] if bias != nullptr)
// M=4096, N=1024, K=1024. BM=BN=128, BK=16, 256 threads, 8x8 per thread.
// ---------------------------------------------------------------------------
__global__ __launch_bounds__(256, 2)
void gemm_nt_kernel(const float* __restrict__ A, const float* __restrict__ W,
                    const float* __restrict__ bias, float* __restrict__ C) {
    const int K = D_MODEL, N = D_MODEL;
    __shared__ float as[16][132];   // [k][m], pad 132 (16B-aligned rows)
    __shared__ float bs[16][132];   // [k][n]

    const int t  = threadIdx.x;
    const int tx = t & 15;
    const int ty = t >> 4;
    const int m0 = blockIdx.y * 128;
    const int n0 = blockIdx.x * 128;

    float acc[8][8];
#pragma unroll
    for (int i = 0; i < 8; i++)
#pragma unroll
        for (int j = 0; j < 8; j++) acc[i][j] = 0.f;

    const float* Ab = A + (size_t)m0 * K;
    const float* Wb = W + (size_t)n0 * K;

    for (int k0 = 0; k0 < K; k0 += 16) {
        // load tiles (transposed into [k][m] layout)
#pragma unroll
        for (int l = 0; l < 2; l++) {
            int fid = t + l * 256;          // 0..511
            int m   = fid >> 2;             // 0..127
            int kq  = (fid & 3) << 2;       // 0,4,8,12
            float4 av = *(const float4*)(Ab + (size_t)m * K + k0 + kq);
            as[kq + 0][m] = av.x; as[kq + 1][m] = av.y;
            as[kq + 2][m] = av.z; as[kq + 3][m] = av.w;
            float4 bv = *(const float4*)(Wb + (size_t)m * K + k0 + kq);
            bs[kq + 0][m] = bv.x; bs[kq + 1][m] = bv.y;
            bs[kq + 2][m] = bv.z; bs[kq + 3][m] = bv.w;
        }
        __syncthreads();

#pragma unroll
        for (int k = 0; k < 16; k++) {
            float af[8], bf[8];
            *(float4*)&af[0] = *(const float4*)&as[k][ty * 8];
            *(float4*)&af[4] = *(const float4*)&as[k][ty * 8 + 4];
            *(float4*)&bf[0] = *(const float4*)&bs[k][tx * 8];
            *(float4*)&bf[4] = *(const float4*)&bs[k][tx * 8 + 4];
#pragma unroll
            for (int i = 0; i < 8; i++)
#pragma unroll
                for (int j = 0; j < 8; j++)
                    acc[i][j] += af[i] * bf[j];
        }
        __syncthreads();
    }

    float bv[8];
#pragma unroll
    for (int j = 0; j < 8; j++) bv[j] = bias ? bias[n0 + tx * 8 + j] : 0.f;

#pragma unroll
    for (int i = 0; i < 8; i++) {
        float* cp = C + (size_t)(m0 + ty * 8 + i) * N + n0 + tx * 8;
        float4 o0 = make_float4(acc[i][0] + bv[0], acc[i][1] + bv[1],
                                acc[i][2] + bv[2], acc[i][3] + bv[3]);
        float4 o1 = make_float4(acc[i][4] + bv[4], acc[i][5] + bv[5],
                                acc[i][6] + bv[6], acc[i][7] + bv[7]);
        *(float4*)cp       = o0;
        *(float4*)(cp + 4) = o1;
    }
}

// ---------------------------------------------------------------------------
// Flash attention (fp32, online softmax).
// Grid: (S/64, H, B). 256 threads as 16x16. Each CTA: 64 query rows, one head.
// Loops over 32 KV blocks of 64 keys. SMEM: qt/kt [d][i|j], vs [j][d],
// ps [i][j], all padded to 65 floats/row (conflict-free).
// ---------------------------------------------------------------------------
#define ATTN_SMEM_FLOATS (4 * 64 * 65)
#define ATTN_SMEM_BYTES  (ATTN_SMEM_FLOATS * sizeof(float))

__global__ __launch_bounds__(256)
void attn_kernel(const float* __restrict__ Qg, const float* __restrict__ Kg,
                 const float* __restrict__ Vg, float* __restrict__ Og) {
    extern __shared__ float sm[];
    float* qt = sm;                 // qt[d*65 + i], Q^T (pre-scaled)
    float* kt = sm + 64 * 65;       // kt[d*65 + j], K^T
    float* vs = sm + 2 * 64 * 65;   // vs[j*65 + d], V
    float* ps = sm + 3 * 64 * 65;   // ps[i*65 + j], P

    const int t  = threadIdx.x;
    const int tx = t & 15;
    const int ty = t >> 4;
    const int h  = blockIdx.y;
    const int b  = blockIdx.z;
    const int m0 = b * SEQ + blockIdx.x * 64;   // global query row base
    const int cb = h * DK;                      // column base in [M,1024]

    // Load Q tile (scaled by 1/sqrt(Dk) = 0.125)
#pragma unroll
    for (int r = 0; r < 16; r++) {
        int idx = t + r * 256;
        int i = idx >> 6, d = idx & 63;
        qt[d * 65 + i] = Qg[(size_t)(m0 + i) * D_MODEL + cb + d] * 0.125f;
    }

    float m_i[4], l_i[4], o[4][4];
#pragma unroll
    for (int ii = 0; ii < 4; ii++) {
        m_i[ii] = -1e30f;
        l_i[ii] = 0.f;
#pragma unroll
        for (int kk = 0; kk < 4; kk++) o[ii][kk] = 0.f;
    }

    for (int kv = 0; kv < SEQ / 64; kv++) {
        const int k0 = b * SEQ + kv * 64;
        __syncthreads();   // previous O-GEMM done before overwriting kt/vs
#pragma unroll
        for (int r = 0; r < 16; r++) {
            int idx = t + r * 256;
            int j = idx >> 6, d = idx & 63;
            kt[d * 65 + j] = Kg[(size_t)(k0 + j) * D_MODEL + cb + d];
            vs[j * 65 + d] = Vg[(size_t)(k0 + j) * D_MODEL + cb + d];
        }
        __syncthreads();

        // S = Q K^T (scale already folded into Q)
        float s[4][4];
#pragma unroll
        for (int ii = 0; ii < 4; ii++)
#pragma unroll
            for (int jj = 0; jj < 4; jj++) s[ii][jj] = 0.f;

#pragma unroll 4
        for (int d = 0; d < 64; d++) {
            float qf[4], kf[4];
#pragma unroll
            for (int ii = 0; ii < 4; ii++) qf[ii] = qt[d * 65 + ty * 4 + ii];
#pragma unroll
            for (int jj = 0; jj < 4; jj++) kf[jj] = kt[d * 65 + tx * 4 + jj];
#pragma unroll
            for (int ii = 0; ii < 4; ii++)
#pragma unroll
                for (int jj = 0; jj < 4; jj++)
                    s[ii][jj] += qf[ii] * kf[jj];
        }

        // online softmax update (row reductions across the 16 tx lanes)
#pragma unroll
        for (int ii = 0; ii < 4; ii++) {
            float mb = fmaxf(fmaxf(s[ii][0], s[ii][1]), fmaxf(s[ii][2], s[ii][3]));
#pragma unroll
            for (int off = 1; off < 16; off <<= 1)
                mb = fmaxf(mb, __shfl_xor_sync(0xffffffffu, mb, off));
            float mn    = fmaxf(m_i[ii], mb);
            float alpha = __expf(m_i[ii] - mn);
            float rs = 0.f;
#pragma unroll
            for (int jj = 0; jj < 4; jj++) {
                s[ii][jj] = __expf(s[ii][jj] - mn);
                rs += s[ii][jj];
            }
#pragma unroll
            for (int off = 1; off < 16; off <<= 1)
                rs += __shfl_xor_sync(0xffffffffu, rs, off);
            l_i[ii] = l_i[ii] * alpha + rs;
            m_i[ii] = mn;
#pragma unroll
            for (int kk = 0; kk < 4; kk++) o[ii][kk] *= alpha;
#pragma unroll
            for (int jj = 0; jj < 4; jj++)
                ps[(ty * 4 + ii) * 65 + tx * 4 + jj] = s[ii][jj];
        }
        __syncthreads();

        // O += P @ V
#pragma unroll 4
        for (int j = 0; j < 64; j++) {
            float pf[4], vf[4];
#pragma unroll
            for (int ii = 0; ii < 4; ii++) pf[ii] = ps[(ty * 4 + ii) * 65 + j];
#pragma unroll
            for (int kk = 0; kk < 4; kk++) vf[kk] = vs[j * 65 + tx * 4 + kk];
#pragma unroll
            for (int ii = 0; ii < 4; ii++)
#pragma unroll
                for (int kk = 0; kk < 4; kk++)
                    o[ii][kk] += pf[ii] * vf[kk];
        }
    }

    // finalize: divide by l, write to [M, 1024] layout (head h columns)
#pragma unroll
    for (int ii = 0; ii < 4; ii++) {
        float inv = 1.f / l_i[ii];
        float4 ov = make_float4(o[ii][0] * inv, o[ii][1] * inv,
                                o[ii][2] * inv, o[ii][3] * inv);
        *(float4*)(Og + (size_t)(m0 + ty * 4 + ii) * D_MODEL + cb + tx * 4) = ov;
    }
}

// ---------------------------------------------------------------------------
// Launch: 3 projection GEMMs -> flash attention -> output projection (+bias)
// ---------------------------------------------------------------------------
extern "C" void kernel_launch(void* const* d_in, const int* in_sizes, int n_in,
                              void* d_out, int out_size) {
    const float* x  = (const float*)d_in[0];
    const float* wq = (const float*)d_in[1];
    const float* wk = (const float*)d_in[2];
    const float* wv = (const float*)d_in[3];
    const float* wo = (const float*)d_in[4];
    const float* bo = (const float*)d_in[5];
    float* out = (float*)d_out;

    float *Qp, *Kp, *Vp, *AOp;
    cudaGetSymbolAddress((void**)&Qp,  g_Q);
    cudaGetSymbolAddress((void**)&Kp,  g_K);
    cudaGetSymbolAddress((void**)&Vp,  g_V);
    cudaGetSymbolAddress((void**)&AOp, g_AO);

    cudaFuncSetAttribute(attn_kernel,
                         cudaFuncAttributeMaxDynamicSharedMemorySize,
                         (int)ATTN_SMEM_BYTES);

    dim3 gemm_grid(D_MODEL / 128, M_TOK / 128);   // (8, 32)
    gemm_nt_kernel<<<gemm_grid, 256>>>(x, wq, nullptr, Qp);
    gemm_nt_kernel<<<gemm_grid, 256>>>(x, wk, nullptr, Kp);
    gemm_nt_kernel<<<gemm_grid, 256>>>(x, wv, nullptr, Vp);

    dim3 attn_grid(SEQ / 64, NUM_HEADS, BATCH);   // (32, 16, 2)
    attn_kernel<<<attn_grid, 256, ATTN_SMEM_BYTES>>>(Qp, Kp, Vp, AOp);

    gemm_nt_kernel<<<gemm_grid, 256>>>(AOp, wo, bo, out);
}

// round 15
// speedup vs baseline: 1.0018x; 1.0004x over previous
#include <cuda_runtime.h>
#include <math.h>

// Problem constants
#define D_MODEL   1024
#define NUM_HEADS 16
#define DK        64
#define SEQ       2048
#define BATCH     2
#define M_TOK     (BATCH * SEQ)   // 4096 tokens

// Scratch (device globals — no cudaMalloc allowed)
__device__ float g_Q [M_TOK * D_MODEL];
__device__ float g_K [M_TOK * D_MODEL];
__device__ float g_V [M_TOK * D_MODEL];
__device__ float g_AO[M_TOK * D_MODEL];

// ---------------------------------------------------------------------------
// GEMM (NT): C[m][n] = sum_k A[m][k] * W[n][k]  (+ bias[n] if bias != nullptr)
// M=4096, N=1024, K=1024. BM=BN=128, BK=16, 256 threads, 8x8 per thread.
// ---------------------------------------------------------------------------
__global__ __launch_bounds__(256, 2)
void gemm_nt_kernel(const float* __restrict__ A, const float* __restrict__ W,
                    const float* __restrict__ bias, float* __restrict__ C) {
    const int K = D_MODEL, N = D_MODEL;
    __shared__ float as[16][132];   // [k][m], pad 132 (16B-aligned rows)
    __shared__ float bs[16][132];   // [k][n]

    const int t  = threadIdx.x;
    const int tx = t & 15;
    const int ty = t >> 4;
    const int m0 = blockIdx.y * 128;
    const int n0 = blockIdx.x * 128;

    float acc[8][8];
#pragma unroll
    for (int i = 0; i < 8; i++)
#pragma unroll
        for (int j = 0; j < 8; j++) acc[i][j] = 0.f;

    const float* Ab = A + (size_t)m0 * K;
    const float* Wb = W + (size_t)n0 * K;

    for (int k0 = 0; k0 < K; k0 += 16) {
        // load tiles (transposed into [k][m] layout)
#pragma unroll
        for (int l = 0; l < 2; l++) {
            int fid = t + l * 256;          // 0..511
            int m   = fid >> 2;             // 0..127
            int kq  = (fid & 3) << 2;       // 0,4,8,12
            float4 av = *(const float4*)(Ab + (size_t)m * K + k0 + kq);
            as[kq + 0][m] = av.x; as[kq + 1][m] = av.y;
            as[kq + 2][m] = av.z; as[kq + 3][m] = av.w;
            float4 bv = *(const float4*)(Wb + (size_t)m * K + k0 + kq);
            bs[kq + 0][m] = bv.x; bs[kq + 1][m] = bv.y;
            bs[kq + 2][m] = bv.z; bs[kq + 3][m] = bv.w;
        }
        __syncthreads();

#pragma unroll
        for (int k = 0; k < 16; k++) {
            float af[8], bf[8];
            *(float4*)&af[0] = *(const float4*)&as[k][ty * 8];
            *(float4*)&af[4] = *(const float4*)&as[k][ty * 8 + 4];
            *(float4*)&bf[0] = *(const float4*)&bs[k][tx * 8];
            *(float4*)&bf[4] = *(const float4*)&bs[k][tx * 8 + 4];
#pragma unroll
            for (int i = 0; i < 8; i++)
#pragma unroll
                for (int j = 0; j < 8; j++)
                    acc[i][j] += af[i] * bf[j];
        }
        __syncthreads();
    }

    float bv[8];
#pragma unroll
    for (int j = 0; j < 8; j++) bv[j] = bias ? bias[n0 + tx * 8 + j] : 0.f;

#pragma unroll
    for (int i = 0; i < 8; i++) {
        float* cp = C + (size_t)(m0 + ty * 8 + i) * N + n0 + tx * 8;
        float4 o0 = make_float4(acc[i][0] + bv[0], acc[i][1] + bv[1],
                                acc[i][2] + bv[2], acc[i][3] + bv[3]);
        float4 o1 = make_float4(acc[i][4] + bv[4], acc[i][5] + bv[5],
                                acc[i][6] + bv[6], acc[i][7] + bv[7]);
        *(float4*)cp       = o0;
        *(float4*)(cp + 4) = o1;
    }
}

// ---------------------------------------------------------------------------
// Flash attention (fp32, online softmax).
// Grid: (S/64, H, B). 256 threads as 16x16. Each CTA: 64 query rows, one head.
// Loops over 32 KV blocks of 64 keys. SMEM: qt/kt [d][i|j], vs [j][d],
// ps [i][j], all padded to 65 floats/row (conflict-free).
// ---------------------------------------------------------------------------
#define ATTN_SMEM_FLOATS (4 * 64 * 65)
#define ATTN_SMEM_BYTES  (ATTN_SMEM_FLOATS * sizeof(float))

__global__ __launch_bounds__(256)
void attn_kernel(const float* __restrict__ Qg, const float* __restrict__ Kg,
                 const float* __restrict__ Vg, float* __restrict__ Og) {
    extern __shared__ float sm[];
    float* qt = sm;                 // qt[d*65 + i], Q^T (pre-scaled)
    float* kt = sm + 64 * 65;       // kt[d*65 + j], K^T
    float* vs = sm + 2 * 64 * 65;   // vs[j*65 + d], V
    float* ps = sm + 3 * 64 * 65;   // ps[i*65 + j], P

    const int t  = threadIdx.x;
    const int tx = t & 15;
    const int ty = t >> 4;
    const int h  = blockIdx.y;
    const int b  = blockIdx.z;
    const int m0 = b * SEQ + blockIdx.x * 64;   // global query row base
    const int cb = h * DK;                      // column base in [M,1024]

    // Load Q tile (scaled by 1/sqrt(Dk) = 0.125)
#pragma unroll
    for (int r = 0; r < 16; r++) {
        int idx = t + r * 256;
        int i = idx >> 6, d = idx & 63;
        qt[d * 65 + i] = Qg[(size_t)(m0 + i) * D_MODEL + cb + d] * 0.125f;
    }

    float m_i[4], l_i[4], o[4][4];
#pragma unroll
    for (int ii = 0; ii < 4; ii++) {
        m_i[ii] = -1e30f;
        l_i[ii] = 0.f;
#pragma unroll
        for (int kk = 0; kk < 4; kk++) o[ii][kk] = 0.f;
    }

    for (int kv = 0; kv < SEQ / 64; kv++) {
        const int k0 = b * SEQ + kv * 64;
        __syncthreads();   // previous O-GEMM done before overwriting kt/vs
#pragma unroll
        for (int r = 0; r < 16; r++) {
            int idx = t + r * 256;
            int j = idx >> 6, d = idx & 63;
            kt[d * 65 + j] = Kg[(size_t)(k0 + j) * D_MODEL + cb + d];
            vs[j * 65 + d] = Vg[(size_t)(k0 + j) * D_MODEL + cb + d];
        }
        __syncthreads();

        // S = Q K^T (scale already folded into Q)
        float s[4][4];
#pragma unroll
        for (int ii = 0; ii < 4; ii++)
#pragma unroll
            for (int jj = 0; jj < 4; jj++) s[ii][jj] = 0.f;

#pragma unroll 4
        for (int d = 0; d < 64; d++) {
            float qf[4], kf[4];
#pragma unroll
            for (int ii = 0; ii < 4; ii++) qf[ii] = qt[d * 65 + ty * 4 + ii];
#pragma unroll
            for (int jj = 0; jj < 4; jj++) kf[jj] = kt[d * 65 + tx * 4 + jj];
#pragma unroll
            for (int ii = 0; ii < 4; ii++)
#pragma unroll
                for (int jj = 0; jj < 4; jj++)
                    s[ii][jj] += qf[ii] * kf[jj];
        }

        // online softmax update (row reductions across the 16 tx lanes)
#pragma unroll
        for (int ii = 0; ii < 4; ii++) {
            float mb = fmaxf(fmaxf(s[ii][0], s[ii][1]), fmaxf(s[ii][2], s[ii][3]));
#pragma unroll
            for (int off = 1; off < 16; off <<= 1)
                mb = fmaxf(mb, __shfl_xor_sync(0xffffffffu, mb, off));
            float mn    = fmaxf(m_i[ii], mb);
            float alpha = __expf(m_i[ii] - mn);
            float rs = 0.f;
#pragma unroll
            for (int jj = 0; jj < 4; jj++) {
                s[ii][jj] = __expf(s[ii][jj] - mn);
                rs += s[ii][jj];
            }
#pragma unroll
            for (int off = 1; off < 16; off <<= 1)
                rs += __shfl_xor_sync(0xffffffffu, rs, off);
            l_i[ii] = l_i[ii] * alpha + rs;
            m_i[ii] = mn;
#pragma unroll
            for (int kk = 0; kk < 4; kk++) o[ii][kk] *= alpha;
#pragma unroll
            for (int jj = 0; jj < 4; jj++)
                ps[(ty * 4 + ii) * 65 + tx * 4 + jj] = s[ii][jj];
        }
        __syncthreads();

        // O += P @ V
#pragma unroll 4
        for (int j = 0; j < 64; j++) {
            float pf[4], vf[4];
#pragma unroll
            for (int ii = 0; ii < 4; ii++) pf[ii] = ps[(ty * 4 + ii) * 65 + j];
#pragma unroll
            for (int kk = 0; kk < 4; kk++) vf[kk] = vs[j * 65 + tx * 4 + kk];
#pragma unroll
            for (int ii = 0; ii < 4; ii++)
#pragma unroll
                for (int kk = 0; kk < 4; kk++)
                    o[ii][kk] += pf[ii] * vf[kk];
        }
    }

    // finalize: divide by l, write to [M, 1024] layout (head h columns)
#pragma unroll
    for (int ii = 0; ii < 4; ii++) {
        float inv = 1.f / l_i[ii];
        float4 ov = make_float4(o[ii][0] * inv, o[ii][1] * inv,
                                o[ii][2] * inv, o[ii][3] * inv);
        *(float4*)(Og + (size_t)(m0 + ty * 4 + ii) * D_MODEL + cb + tx * 4) = ov;
    }
}

// ---------------------------------------------------------------------------
// Launch: 3 projection GEMMs -> flash attention -> output projection (+bias)
// ---------------------------------------------------------------------------
extern "C" void kernel_launch(void* const* d_in, const int* in_sizes, int n_in,
                              void* d_out, int out_size) {
    const float* x  = (const float*)d_in[0];
    const float* wq = (const float*)d_in[1];
    const float* wk = (const float*)d_in[2];
    const float* wv = (const float*)d_in[3];
    const float* wo = (const float*)d_in[4];
    const float* bo = (const float*)d_in[5];
    float* out = (float*)d_out;

    float *Qp, *Kp, *Vp, *AOp;
    cudaGetSymbolAddress((void**)&Qp,  g_Q);
    cudaGetSymbolAddress((void**)&Kp,  g_K);
    cudaGetSymbolAddress((void**)&Vp,  g_V);
    cudaGetSymbolAddress((void**)&AOp, g_AO);

    cudaFuncSetAttribute(attn_kernel,
                         cudaFuncAttributeMaxDynamicSharedMemorySize,
                         (int)ATTN_SMEM_BYTES);

    dim3 gemm_grid(D_MODEL / 128, M_TOK / 128);   // (8, 32)
    gemm_nt_kernel<<<gemm_grid, 256>>>(x, wq, nullptr, Qp);
    gemm_nt_kernel<<<gemm_grid, 256>>>(x, wk, nullptr, Kp);
    gemm_nt_kernel<<<gemm_grid, 256>>>(x, wv, nullptr, Vp);

    dim3 attn_grid(SEQ / 64, NUM_HEADS, BATCH);   // (32, 16, 2)
    attn_kernel<<<attn_grid, 256, ATTN_SMEM_BYTES>>>(Qp, Kp, Vp, AOp);

    gemm_nt_kernel<<<gemm_grid, 256>>>(AOp, wo, bo, out);
}

// round 16
// speedup vs baseline: 1.0030x; 1.0012x over previous
#include <cuda_runtime.h>
#include <math.h>

// Problem constants
#define D_MODEL   1024
#define NUM_HEADS 16
#define DK        64
#define SEQ       2048
#define BATCH     2
#define M_TOK     (BATCH * SEQ)   // 4096 tokens

// Scratch (device globals — no cudaMalloc allowed)
__device__ float g_Q [M_TOK * D_MODEL];
__device__ float g_K [M_TOK * D_MODEL];
__device__ float g_V [M_TOK * D_MODEL];
__device__ float g_AO[M_TOK * D_MODEL];

// ---------------------------------------------------------------------------
// GEMM (NT): C[m][n] = sum_k A[m][k] * W[n][k]  (+ bias[n] if bias != nullptr)
// M=4096, N=1024, K=1024. BM=BN=128, BK=16, 256 threads, 8x8 per thread.
// ---------------------------------------------------------------------------
__global__ __launch_bounds__(256, 2)
void gemm_nt_kernel(const float* __restrict__ A, const float* __restrict__ W,
                    const float* __restrict__ bias, float* __restrict__ C) {
    const int K = D_MODEL, N = D_MODEL;
    __shared__ float as[16][132];   // [k][m], pad 132 (16B-aligned rows)
    __shared__ float bs[16][132];   // [k][n]

    const int t  = threadIdx.x;
    const int tx = t & 15;
    const int ty = t >> 4;
    const int m0 = blockIdx.y * 128;
    const int n0 = blockIdx.x * 128;

    float acc[8][8];
#pragma unroll
    for (int i = 0; i < 8; i++)
#pragma unroll
        for (int j = 0; j < 8; j++) acc[i][j] = 0.f;

    const float* Ab = A + (size_t)m0 * K;
    const float* Wb = W + (size_t)n0 * K;

    for (int k0 = 0; k0 < K; k0 += 16) {
        // load tiles (transposed into [k][m] layout)
#pragma unroll
        for (int l = 0; l < 2; l++) {
            int fid = t + l * 256;          // 0..511
            int m   = fid >> 2;             // 0..127
            int kq  = (fid & 3) << 2;       // 0,4,8,12
            float4 av = *(const float4*)(Ab + (size_t)m * K + k0 + kq);
            as[kq + 0][m] = av.x; as[kq + 1][m] = av.y;
            as[kq + 2][m] = av.z; as[kq + 3][m] = av.w;
            float4 bv = *(const float4*)(Wb + (size_t)m * K + k0 + kq);
            bs[kq + 0][m] = bv.x; bs[kq + 1][m] = bv.y;
            bs[kq + 2][m] = bv.z; bs[kq + 3][m] = bv.w;
        }
        __syncthreads();

#pragma unroll
        for (int k = 0; k < 16; k++) {
            float af[8], bf[8];
            *(float4*)&af[0] = *(const float4*)&as[k][ty * 8];
            *(float4*)&af[4] = *(const float4*)&as[k][ty * 8 + 4];
            *(float4*)&bf[0] = *(const float4*)&bs[k][tx * 8];
            *(float4*)&bf[4] = *(const float4*)&bs[k][tx * 8 + 4];
#pragma unroll
            for (int i = 0; i < 8; i++)
#pragma unroll
                for (int j = 0; j < 8; j++)
                    acc[i][j] += af[i] * bf[j];
        }
        __syncthreads();
    }

    float bv[8];
#pragma unroll
    for (int j = 0; j < 8; j++) bv[j] = bias ? bias[n0 + tx * 8 + j] : 0.f;

#pragma unroll
    for (int i = 0; i < 8; i++) {
        float* cp = C + (size_t)(m0 + ty * 8 + i) * N + n0 + tx * 8;
        float4 o0 = make_float4(acc[i][0] + bv[0], acc[i][1] + bv[1],
                                acc[i][2] + bv[2], acc[i][3] + bv[3]);
        float4 o1 = make_float4(acc[i][4] + bv[4], acc[i][5] + bv[5],
                                acc[i][6] + bv[6], acc[i][7] + bv[7]);
        *(float4*)cp       = o0;
        *(float4*)(cp + 4) = o1;
    }
}

// ---------------------------------------------------------------------------
// Flash attention (fp32, online softmax).
// Grid: (S/64, H, B). 256 threads as 16x16. Each CTA: 64 query rows, one head.
// Loops over 32 KV blocks of 64 keys. SMEM: qt/kt [d][i|j], vs [j][d],
// ps [i][j], all padded to 65 floats/row (conflict-free).
// ---------------------------------------------------------------------------
#define ATTN_SMEM_FLOATS (4 * 64 * 65)
#define ATTN_SMEM_BYTES  (ATTN_SMEM_FLOATS * sizeof(float))

__global__ __launch_bounds__(256)
void attn_kernel(const float* __restrict__ Qg, const float* __restrict__ Kg,
                 const float* __restrict__ Vg, float* __restrict__ Og) {
    extern __shared__ float sm[];
    float* qt = sm;                 // qt[d*65 + i], Q^T (pre-scaled)
    float* kt = sm + 64 * 65;       // kt[d*65 + j], K^T
    float* vs = sm + 2 * 64 * 65;   // vs[j*65 + d], V
    float* ps = sm + 3 * 64 * 65;   // ps[i*65 + j], P

    const int t  = threadIdx.x;
    const int tx = t & 15;
    const int ty = t >> 4;
    const int h  = blockIdx.y;
    const int b  = blockIdx.z;
    const int m0 = b * SEQ + blockIdx.x * 64;   // global query row base
    const int cb = h * DK;                      // column base in [M,1024]

    // Load Q tile (scaled by 1/sqrt(Dk) = 0.125)
#pragma unroll
    for (int r = 0; r < 16; r++) {
        int idx = t + r * 256;
        int i = idx >> 6, d = idx & 63;
        qt[d * 65 + i] = Qg[(size_t)(m0 + i) * D_MODEL + cb + d] * 0.125f;
    }

    float m_i[4], l_i[4], o[4][4];
#pragma unroll
    for (int ii = 0; ii < 4; ii++) {
        m_i[ii] = -1e30f;
        l_i[ii] = 0.f;
#pragma unroll
        for (int kk = 0; kk < 4; kk++) o[ii][kk] = 0.f;
    }

    for (int kv = 0; kv < SEQ / 64; kv++) {
        const int k0 = b * SEQ + kv * 64;
        __syncthreads();   // previous O-GEMM done before overwriting kt/vs
#pragma unroll
        for (int r = 0; r < 16; r++) {
            int idx = t + r * 256;
            int j = idx >> 6, d = idx & 63;
            kt[d * 65 + j] = Kg[(size_t)(k0 + j) * D_MODEL + cb + d];
            vs[j * 65 + d] = Vg[(size_t)(k0 + j) * D_MODEL + cb + d];
        }
        __syncthreads();

        // S = Q K^T (scale already folded into Q)
        float s[4][4];
#pragma unroll
        for (int ii = 0; ii < 4; ii++)
#pragma unroll
            for (int jj = 0; jj < 4; jj++) s[ii][jj] = 0.f;

#pragma unroll 4
        for (int d = 0; d < 64; d++) {
            float qf[4], kf[4];
#pragma unroll
            for (int ii = 0; ii < 4; ii++) qf[ii] = qt[d * 65 + ty * 4 + ii];
#pragma unroll
            for (int jj = 0; jj < 4; jj++) kf[jj] = kt[d * 65 + tx * 4 + jj];
#pragma unroll
            for (int ii = 0; ii < 4; ii++)
#pragma unroll
                for (int jj = 0; jj < 4; jj++)
                    s[ii][jj] += qf[ii] * kf[jj];
        }

        // online softmax update (row reductions across the 16 tx lanes)
#pragma unroll
        for (int ii = 0; ii < 4; ii++) {
            float mb = fmaxf(fmaxf(s[ii][0], s[ii][1]), fmaxf(s[ii][2], s[ii][3]));
#pragma unroll
            for (int off = 1; off < 16; off <<= 1)
                mb = fmaxf(mb, __shfl_xor_sync(0xffffffffu, mb, off));
            float mn    = fmaxf(m_i[ii], mb);
            float alpha = __expf(m_i[ii] - mn);
            float rs = 0.f;
#pragma unroll
            for (int jj = 0; jj < 4; jj++) {
                s[ii][jj] = __expf(s[ii][jj] - mn);
                rs += s[ii][jj];
            }
#pragma unroll
            for (int off = 1; off < 16; off <<= 1)
                rs += __shfl_xor_sync(0xffffffffu, rs, off);
            l_i[ii] = l_i[ii] * alpha + rs;
            m_i[ii] = mn;
#pragma unroll
            for (int kk = 0; kk < 4; kk++) o[ii][kk] *= alpha;
#pragma unroll
            for (int jj = 0; jj < 4; jj++)
                ps[(ty * 4 + ii) * 65 + tx * 4 + jj] = s[ii][jj];
        }
        __syncthreads();

        // O += P @ V
#pragma unroll 4
        for (int j = 0; j < 64; j++) {
            float pf[4], vf[4];
#pragma unroll
            for (int ii = 0; ii < 4; ii++) pf[ii] = ps[(ty * 4 + ii) * 65 + j];
#pragma unroll
            for (int kk = 0; kk < 4; kk++) vf[kk] = vs[j * 65 + tx * 4 + kk];
#pragma unroll
            for (int ii = 0; ii < 4; ii++)
#pragma unroll
                for (int kk = 0; kk < 4; kk++)
                    o[ii][kk] += pf[ii] * vf[kk];
        }
    }

    // finalize: divide by l, write to [M, 1024] layout (head h columns)
#pragma unroll
    for (int ii = 0; ii < 4; ii++) {
        float inv = 1.f / l_i[ii];
        float4 ov = make_float4(o[ii][0] * inv, o[ii][1] * inv,
                                o[ii][2] * inv, o[ii][3] * inv);
        *(float4*)(Og + (size_t)(m0 + ty * 4 + ii) * D_MODEL + cb + tx * 4) = ov;
    }
}

// ---------------------------------------------------------------------------
// Launch: 3 projection GEMMs -> flash attention -> output projection (+bias)
// ---------------------------------------------------------------------------
extern "C" void kernel_launch(void* const* d_in, const int* in_sizes, int n_in,
                              void* d_out, int out_size) {
    const float* x  = (const float*)d_in[0];
    const float* wq = (const float*)d_in[1];
    const float* wk = (const float*)d_in[2];
    const float* wv = (const float*)d_in[3];
    const float* wo = (const float*)d_in[4];
    const float* bo = (const float*)d_in[5];
    float* out = (float*)d_out;

    float *Qp, *Kp, *Vp, *AOp;
    cudaGetSymbolAddress((void**)&Qp,  g_Q);
    cudaGetSymbolAddress((void**)&Kp,  g_K);
    cudaGetSymbolAddress((void**)&Vp,  g_V);
    cudaGetSymbolAddress((void**)&AOp, g_AO);

    cudaFuncSetAttribute(attn_kernel,
                         cudaFuncAttributeMaxDynamicSharedMemorySize,
                         (int)ATTN_SMEM_BYTES);

    dim3 gemm_grid(D_MODEL / 128, M_TOK / 128);   // (8, 32)
    gemm_nt_kernel<<<gemm_grid, 256>>>(x, wq, nullptr, Qp);
    gemm_nt_kernel<<<gemm_grid, 256>>>(x, wk, nullptr, Kp);
    gemm_nt_kernel<<<gemm_grid, 256>>>(x, wv, nullptr, Vp);

    dim3 attn_grid(SEQ / 64, NUM_HEADS, BATCH);   // (32, 16, 2)
    attn_kernel<<<attn_grid, 256, ATTN_SMEM_BYTES>>>(Qp, Kp, Vp, AOp);

    gemm_nt_kernel<<<gemm_grid, 256>>>(AOp, wo, bo, out);
}